// round 12
// baseline (speedup 1.0000x reference)
#include <cuda_runtime.h>
#include <cuda_bf16.h>
#include <cuda_fp16.h>
#include <cstdint>
#include <cstddef>

#define EPSV 1e-5f
#define NTOK 4096

// Scratch (no allocations allowed)
__device__ float g_qkv[2u * 512u * 4096u];   // 16 MB fp32 qkv activations
__device__ float g_y[2u * 256u * 4096u];     //  8 MB attention + pe output

__device__ __forceinline__ uint32_t pack_h2(float a, float b) {
    __half2 h = __floats2half2_rn(a, b);
    return *reinterpret_cast<uint32_t*>(&h);
}
// fp16 hi/lo split of a float pair
__device__ __forceinline__ uint32_t pack_f16_hi(float a, float b, uint32_t& lo) {
    __half ah = __float2half_rn(a), bh = __float2half_rn(b);
    __half2 L = __floats2half2_rn(a - __half2float(ah), b - __half2float(bh));
    lo = *reinterpret_cast<uint32_t*>(&L);
    __half2 H = __halves2half2(ah, bh);
    return *reinterpret_cast<uint32_t*>(&H);
}

// mma.sync m16n8k16 row.col f32 += f16*f16
__device__ __forceinline__ void mma16816(float* c, const uint32_t* a, const uint32_t* b) {
    asm volatile(
        "mma.sync.aligned.m16n8k16.row.col.f32.f16.f16.f32 "
        "{%0,%1,%2,%3}, {%4,%5,%6,%7}, {%8,%9}, {%0,%1,%2,%3};"
        : "+f"(c[0]), "+f"(c[1]), "+f"(c[2]), "+f"(c[3])
        : "r"(a[0]), "r"(a[1]), "r"(a[2]), "r"(a[3]), "r"(b[0]), "r"(b[1]));
}

// depthwise 3x3 stencil (pad 1) on one V channel at token t (64x64 image)
__device__ __forceinline__ float pe_stencil(const float* __restrict__ vch,
                                            const float* __restrict__ wc, int t) {
    int py = t >> 6, px = t & 63;
    float s = 0.f;
    #pragma unroll
    for (int dy = -1; dy <= 1; dy++) {
        int yy = py + dy;
        if (yy < 0 || yy > 63) continue;
        #pragma unroll
        for (int dx = -1; dx <= 1; dx++) {
            int xx = px + dx;
            if (xx < 0 || xx > 63) continue;
            s += vch[yy * 64 + xx] * wc[(dy + 1) * 3 + (dx + 1)];
        }
    }
    return s;
}

// ---------------------------------------------------------------------------
// HMMA GEMM + folded BatchNorm. fp16 2-term: A single fp16, B hi/lo fp16.
// Unchanged from R11 (proven).
// ---------------------------------------------------------------------------
__global__ __launch_bounds__(256) void gemm_bn_tc(
    const float* __restrict__ A, const float* __restrict__ B, float* __restrict__ C,
    int M, int N, int K,
    const float* __restrict__ gg, const float* __restrict__ bb,
    const float* __restrict__ mm, const float* __restrict__ vv)
{
    __shared__ uint32_t sA[128][20];   // [m][kpair 0..15], single fp16
    __shared__ uint32_t sB[64][36];    // [n][kpair]: hi 0..15, lo 16..31

    const int tid = threadIdx.x, wid = tid >> 5, lane = tid & 31;
    const int tg = lane >> 2, t4 = lane & 3;
    const int m0 = blockIdx.y * 128, n0 = blockIdx.x * 64;
    const float* Bp = B + (size_t)blockIdx.z * (size_t)K * N;
    float* Cp = C + (size_t)blockIdx.z * (size_t)M * N;

    const int rA = tid >> 1, hA = tid & 1;
    const int nB = tid & 63, kp0 = tid >> 6;
    const int nchunk = K >> 5;

    float4 axf[4];
    float bxk[4][2];
    {
        const float* ap = A + (size_t)(m0 + rA) * K + hA * 16;
        #pragma unroll
        for (int i = 0; i < 4; i++) axf[i] = *(const float4*)(ap + 4 * i);
        #pragma unroll
        for (int i = 0; i < 4; i++) {
            int kp = kp0 + 4 * i;
            bxk[i][0] = Bp[(size_t)(2 * kp) * N + n0 + nB];
            bxk[i][1] = Bp[(size_t)(2 * kp + 1) * N + n0 + nB];
        }
    }

    float c[8][4];
    #pragma unroll
    for (int i = 0; i < 8; i++)
        #pragma unroll
        for (int j = 0; j < 4; j++) c[i][j] = 0.f;

    for (int ch = 0; ch < nchunk; ch++) {
        if (ch) __syncthreads();
        #pragma unroll
        for (int i = 0; i < 4; i++) {
            int kp = hA * 8 + 2 * i;
            sA[rA][kp]     = pack_h2(axf[i].x, axf[i].y);
            sA[rA][kp + 1] = pack_h2(axf[i].z, axf[i].w);
        }
        #pragma unroll
        for (int i = 0; i < 4; i++) {
            uint32_t lo, hi = pack_f16_hi(bxk[i][0], bxk[i][1], lo);
            sB[nB][kp0 + 4 * i] = hi;
            sB[nB][16 + kp0 + 4 * i] = lo;
        }
        __syncthreads();

        if (ch + 1 < nchunk) {
            const int k0 = (ch + 1) * 32;
            const float* ap = A + (size_t)(m0 + rA) * K + k0 + hA * 16;
            #pragma unroll
            for (int i = 0; i < 4; i++) axf[i] = *(const float4*)(ap + 4 * i);
            #pragma unroll
            for (int i = 0; i < 4; i++) {
                int kp = kp0 + 4 * i;
                bxk[i][0] = Bp[(size_t)(k0 + 2 * kp) * N + n0 + nB];
                bxk[i][1] = Bp[(size_t)(k0 + 2 * kp + 1) * N + n0 + nB];
            }
        }

        const int r0 = wid * 16 + tg, r1 = r0 + 8;
        #pragma unroll
        for (int ks = 0; ks < 2; ks++) {
            int ca = t4 + 8 * ks;
            uint32_t ah[4] = { sA[r0][ca],     sA[r1][ca],
                               sA[r0][ca + 4], sA[r1][ca + 4] };
            #pragma unroll
            for (int nt = 0; nt < 8; nt++) {
                int n = nt * 8 + tg;
                uint32_t bh_[2] = { sB[n][ca], sB[n][ca + 4] };
                uint32_t bl_[2] = { sB[n][16 + ca], sB[n][16 + ca + 4] };
                mma16816(c[nt], ah, bh_);
                mma16816(c[nt], ah, bl_);
            }
        }
    }

    const int r0 = m0 + wid * 16 + tg, r1 = r0 + 8;
    float sc0 = gg[r0] * rsqrtf(vv[r0] + EPSV), sh0 = bb[r0] - mm[r0] * sc0;
    float sc1 = gg[r1] * rsqrtf(vv[r1] + EPSV), sh1 = bb[r1] - mm[r1] * sc1;
    #pragma unroll
    for (int nt = 0; nt < 8; nt++) {
        int n = n0 + nt * 8 + 2 * t4;
        *(float2*)&Cp[(size_t)r0 * N + n] = make_float2(c[nt][0] * sc0 + sh0,
                                                        c[nt][1] * sc0 + sh0);
        *(float2*)&Cp[(size_t)r1 * N + n] = make_float2(c[nt][2] * sc1 + sh1,
                                                        c[nt][3] * sc1 + sh1);
    }
}

// ---------------------------------------------------------------------------
// Flash attention (fp16 HMMA, single-term) + FUSED depthwise-3x3 PE + BN.
// Inner loop unchanged from R11; epilogue adds pe for this CTA's own tile.
// ---------------------------------------------------------------------------
__global__ __launch_bounds__(256, 1) void attn_mma_kernel(
    const float* __restrict__ qkv, float* __restrict__ y,
    const float* __restrict__ pw,
    const float* __restrict__ pg, const float* __restrict__ pb,
    const float* __restrict__ pm, const float* __restrict__ pv)
{
    __shared__ uint32_t sQ[128][20];
    __shared__ uint32_t sK[64][20];
    __shared__ uint32_t sV[64][36];

    const int tid = threadIdx.x, wid = tid >> 5, lane = tid & 31;
    const int tg = lane >> 2;
    const int t4 = lane & 3;
    const int bh = blockIdx.y, bi = bh >> 2, h = bh & 3;
    const int q0 = blockIdx.x * 128;

    const float* qp = qkv + ((size_t)bi * 512 + h * 128) * NTOK;
    const float* kp = qp + (size_t)32 * NTOK;
    const float* vp = qp + (size_t)64 * NTOK;

    {
        const float scale = 0.17677669529663687f;
        int row = tid & 127, dp0 = tid >> 7;
        #pragma unroll
        for (int dp = dp0; dp < 16; dp += 2) {
            float x0 = qp[(size_t)(2 * dp) * NTOK + q0 + row] * scale;
            float x1 = qp[(size_t)(2 * dp + 1) * NTOK + q0 + row] * scale;
            sQ[row][dp] = pack_h2(x0, x1);
        }
    }
    __syncthreads();

    uint32_t qh[2][4];
    {
        int r0 = wid * 16 + tg, r1 = r0 + 8;
        #pragma unroll
        for (int ks = 0; ks < 2; ks++) {
            int cidx = t4 + 8 * ks;
            qh[ks][0] = sQ[r0][cidx];     qh[ks][1] = sQ[r1][cidx];
            qh[ks][2] = sQ[r0][cidx + 4]; qh[ks][3] = sQ[r1][cidx + 4];
        }
    }

    const int kkey = tid & 63, kdp0 = tid >> 6;
    const int vkp = tid & 31, vd0 = tid >> 5;

    float kx[4][2];
    float2 vx[8];
    {
        #pragma unroll
        for (int i = 0; i < 4; i++) {
            int dp = kdp0 + 4 * i;
            kx[i][0] = kp[(size_t)(2 * dp) * NTOK + kkey];
            kx[i][1] = kp[(size_t)(2 * dp + 1) * NTOK + kkey];
        }
        #pragma unroll
        for (int i = 0; i < 8; i++) {
            int d = vd0 + 8 * i;
            vx[i] = *(const float2*)(vp + (size_t)d * NTOK + 2 * vkp);
        }
    }

    float m0 = -3e38f, m1 = -3e38f, l0 = 0.f, l1 = 0.f;
    float yacc[8][4];
    #pragma unroll
    for (int i = 0; i < 8; i++)
        #pragma unroll
        for (int j = 0; j < 4; j++) yacc[i][j] = 0.f;

    for (int blk = 0; blk < 64; blk++) {
        __syncthreads();
        #pragma unroll
        for (int i = 0; i < 4; i++)
            sK[kkey][kdp0 + 4 * i] = pack_h2(kx[i][0], kx[i][1]);
        #pragma unroll
        for (int i = 0; i < 8; i++)
            sV[vd0 + 8 * i][vkp] = pack_h2(vx[i].x, vx[i].y);
        __syncthreads();

        if (blk < 63) {
            const int k0t = (blk + 1) * 64;
            #pragma unroll
            for (int i = 0; i < 4; i++) {
                int dp = kdp0 + 4 * i;
                kx[i][0] = kp[(size_t)(2 * dp) * NTOK + k0t + kkey];
                kx[i][1] = kp[(size_t)(2 * dp + 1) * NTOK + k0t + kkey];
            }
            #pragma unroll
            for (int i = 0; i < 8; i++) {
                int d = vd0 + 8 * i;
                vx[i] = *(const float2*)(vp + (size_t)d * NTOK + k0t + 2 * vkp);
            }
        }

        float s[8][4];
        #pragma unroll
        for (int nt = 0; nt < 8; nt++) {
            s[nt][0] = s[nt][1] = s[nt][2] = s[nt][3] = 0.f;
            int key = nt * 8 + tg;
            #pragma unroll
            for (int ks = 0; ks < 2; ks++) {
                uint32_t b_[2] = { sK[key][t4 + 8 * ks], sK[key][t4 + 4 + 8 * ks] };
                mma16816(s[nt], qh[ks], b_);
            }
        }

        float mx0 = -3e38f, mx1 = -3e38f;
        #pragma unroll
        for (int nt = 0; nt < 8; nt++) {
            mx0 = fmaxf(mx0, fmaxf(s[nt][0], s[nt][1]));
            mx1 = fmaxf(mx1, fmaxf(s[nt][2], s[nt][3]));
        }
        mx0 = fmaxf(mx0, __shfl_xor_sync(0xffffffffu, mx0, 1));
        mx0 = fmaxf(mx0, __shfl_xor_sync(0xffffffffu, mx0, 2));
        mx1 = fmaxf(mx1, __shfl_xor_sync(0xffffffffu, mx1, 1));
        mx1 = fmaxf(mx1, __shfl_xor_sync(0xffffffffu, mx1, 2));
        float mn0 = fmaxf(m0, mx0), mn1 = fmaxf(m1, mx1);
        float al0 = __expf(m0 - mn0), al1 = __expf(m1 - mn1);
        m0 = mn0; m1 = mn1;

        uint32_t p01[8], p23[8];
        float sum0 = 0.f, sum1 = 0.f;
        #pragma unroll
        for (int nt = 0; nt < 8; nt++) {
            float p0 = __expf(s[nt][0] - mn0);
            float p1 = __expf(s[nt][1] - mn0);
            float p2 = __expf(s[nt][2] - mn1);
            float p3 = __expf(s[nt][3] - mn1);
            sum0 += p0 + p1;  sum1 += p2 + p3;
            p01[nt] = pack_h2(p0, p1);
            p23[nt] = pack_h2(p2, p3);
        }
        sum0 += __shfl_xor_sync(0xffffffffu, sum0, 1);
        sum0 += __shfl_xor_sync(0xffffffffu, sum0, 2);
        sum1 += __shfl_xor_sync(0xffffffffu, sum1, 1);
        sum1 += __shfl_xor_sync(0xffffffffu, sum1, 2);
        l0 = l0 * al0 + sum0;
        l1 = l1 * al1 + sum1;

        #pragma unroll
        for (int dt = 0; dt < 8; dt++) {
            yacc[dt][0] *= al0; yacc[dt][1] *= al0;
            yacc[dt][2] *= al1; yacc[dt][3] *= al1;
        }

        #pragma unroll
        for (int ks = 0; ks < 4; ks++) {
            uint32_t a_[4] = { p01[2 * ks], p23[2 * ks], p01[2 * ks + 1], p23[2 * ks + 1] };
            #pragma unroll
            for (int dt = 0; dt < 8; dt++) {
                int dim = dt * 8 + tg;
                uint32_t b_[2] = { sV[dim][t4 + 8 * ks], sV[dim][t4 + 4 + 8 * ks] };
                mma16816(yacc[dt], a_, b_);
            }
        }
    }

    // ---- epilogue: attn/denominator + fused depthwise-3x3 PE + BN ----
    float li0 = 1.f / l0, li1 = 1.f / l1;
    int tok0 = q0 + wid * 16 + tg;
    #pragma unroll
    for (int dt = 0; dt < 8; dt++) {
        int dim = dt * 8 + t4 * 2;           // head-local dim of yacc[dt][0/2]
        #pragma unroll
        for (int dd = 0; dd < 2; dd++) {     // dim, dim+1
            int d = dim + dd;
            int ch = h * 64 + d;             // pe channel
            const float* vch = vp + (size_t)d * NTOK;
            const float* wc = pw + ch * 9;
            float psc = pg[ch] * rsqrtf(pv[ch] + EPSV);
            float psh = pb[ch] - pm[ch] * psc;
            float pe0 = pe_stencil(vch, wc, tok0)     * psc + psh;
            float pe1 = pe_stencil(vch, wc, tok0 + 8) * psc + psh;
            float* o = y + ((size_t)(bh * 64 + d)) * NTOK;
            o[tok0]     = yacc[dt][0 + dd] * li0 + pe0;
            o[tok0 + 8] = yacc[dt][2 + dd] * li1 + pe1;
        }
    }
}

// ---------------------------------------------------------------------------
extern "C" void kernel_launch(void* const* d_in, const int* in_sizes, int n_in,
                              void* d_out, int out_size)
{
    const float* x      = (const float*)d_in[0];
    const float* qkv_w  = (const float*)d_in[1];
    const float* qkv_g  = (const float*)d_in[2];
    const float* qkv_b  = (const float*)d_in[3];
    const float* qkv_m  = (const float*)d_in[4];
    const float* qkv_v  = (const float*)d_in[5];
    const float* proj_w = (const float*)d_in[6];
    const float* proj_g = (const float*)d_in[7];
    const float* proj_b = (const float*)d_in[8];
    const float* proj_m = (const float*)d_in[9];
    const float* proj_v = (const float*)d_in[10];
    const float* pe_w   = (const float*)d_in[11];
    const float* pe_g   = (const float*)d_in[12];
    const float* pe_b   = (const float*)d_in[13];
    const float* pe_m   = (const float*)d_in[14];
    const float* pe_v   = (const float*)d_in[15];
    float* out = (float*)d_out;

    float* qkv_ptr = nullptr;
    float* y_ptr = nullptr;
    cudaGetSymbolAddress((void**)&qkv_ptr, g_qkv);
    cudaGetSymbolAddress((void**)&y_ptr, g_y);

    // 1) QKV 1x1 conv + BN  (512x256 @ 256x4096, per batch)
    gemm_bn_tc<<<dim3(64, 4, 2), 256>>>(qkv_w, x, qkv_ptr, 512, 4096, 256,
                                        qkv_g, qkv_b, qkv_m, qkv_v);
    // 2) HMMA fp16 flash attention + fused PE -> g_y
    attn_mma_kernel<<<dim3(32, 8), 256>>>(qkv_ptr, y_ptr,
                                          pe_w, pe_g, pe_b, pe_m, pe_v);
    // 3) proj 1x1 conv + BN -> out
    gemm_bn_tc<<<dim3(64, 2, 2), 256>>>(proj_w, y_ptr, out, 256, 4096, 256,
                                        proj_g, proj_b, proj_m, proj_v);
}

// round 14
// speedup vs baseline: 1.1596x; 1.1596x over previous
#include <cuda_runtime.h>
#include <cuda_bf16.h>
#include <cuda_fp16.h>
#include <cstdint>
#include <cstddef>

#define EPSV 1e-5f
#define NTOK 4096

// Scratch (no allocations allowed)
__device__ float g_qkv[2u * 512u * 4096u];   // 16 MB fp32 qkv activations
__device__ float g_y[2u * 256u * 4096u];     //  8 MB attention + pe output

__device__ __forceinline__ uint32_t pack_h2(float a, float b) {
    __half2 h = __floats2half2_rn(a, b);
    return *reinterpret_cast<uint32_t*>(&h);
}
// fp16 hi/lo split of a float pair
__device__ __forceinline__ uint32_t pack_f16_hi(float a, float b, uint32_t& lo) {
    __half ah = __float2half_rn(a), bh = __float2half_rn(b);
    __half2 L = __floats2half2_rn(a - __half2float(ah), b - __half2float(bh));
    lo = *reinterpret_cast<uint32_t*>(&L);
    __half2 H = __halves2half2(ah, bh);
    return *reinterpret_cast<uint32_t*>(&H);
}

// mma.sync m16n8k16 row.col f32 += f16*f16
__device__ __forceinline__ void mma16816(float* c, const uint32_t* a, const uint32_t* b) {
    asm volatile(
        "mma.sync.aligned.m16n8k16.row.col.f32.f16.f16.f32 "
        "{%0,%1,%2,%3}, {%4,%5,%6,%7}, {%8,%9}, {%0,%1,%2,%3};"
        : "+f"(c[0]), "+f"(c[1]), "+f"(c[2]), "+f"(c[3])
        : "r"(a[0]), "r"(a[1]), "r"(a[2]), "r"(a[3]), "r"(b[0]), "r"(b[1]));
}

// ---------------------------------------------------------------------------
// HMMA GEMM + folded BatchNorm. fp16 2-term: A single fp16, B hi/lo fp16.
// Unchanged from R11 (proven).
// ---------------------------------------------------------------------------
__global__ __launch_bounds__(256) void gemm_bn_tc(
    const float* __restrict__ A, const float* __restrict__ B, float* __restrict__ C,
    int M, int N, int K,
    const float* __restrict__ gg, const float* __restrict__ bb,
    const float* __restrict__ mm, const float* __restrict__ vv)
{
    __shared__ uint32_t sA[128][20];   // [m][kpair 0..15], single fp16
    __shared__ uint32_t sB[64][36];    // [n][kpair]: hi 0..15, lo 16..31

    const int tid = threadIdx.x, wid = tid >> 5, lane = tid & 31;
    const int tg = lane >> 2, t4 = lane & 3;
    const int m0 = blockIdx.y * 128, n0 = blockIdx.x * 64;
    const float* Bp = B + (size_t)blockIdx.z * (size_t)K * N;
    float* Cp = C + (size_t)blockIdx.z * (size_t)M * N;

    const int rA = tid >> 1, hA = tid & 1;
    const int nB = tid & 63, kp0 = tid >> 6;
    const int nchunk = K >> 5;

    float4 axf[4];
    float bxk[4][2];
    {
        const float* ap = A + (size_t)(m0 + rA) * K + hA * 16;
        #pragma unroll
        for (int i = 0; i < 4; i++) axf[i] = *(const float4*)(ap + 4 * i);
        #pragma unroll
        for (int i = 0; i < 4; i++) {
            int kp = kp0 + 4 * i;
            bxk[i][0] = Bp[(size_t)(2 * kp) * N + n0 + nB];
            bxk[i][1] = Bp[(size_t)(2 * kp + 1) * N + n0 + nB];
        }
    }

    float c[8][4];
    #pragma unroll
    for (int i = 0; i < 8; i++)
        #pragma unroll
        for (int j = 0; j < 4; j++) c[i][j] = 0.f;

    for (int ch = 0; ch < nchunk; ch++) {
        if (ch) __syncthreads();
        #pragma unroll
        for (int i = 0; i < 4; i++) {
            int kp = hA * 8 + 2 * i;
            sA[rA][kp]     = pack_h2(axf[i].x, axf[i].y);
            sA[rA][kp + 1] = pack_h2(axf[i].z, axf[i].w);
        }
        #pragma unroll
        for (int i = 0; i < 4; i++) {
            uint32_t lo, hi = pack_f16_hi(bxk[i][0], bxk[i][1], lo);
            sB[nB][kp0 + 4 * i] = hi;
            sB[nB][16 + kp0 + 4 * i] = lo;
        }
        __syncthreads();

        if (ch + 1 < nchunk) {
            const int k0 = (ch + 1) * 32;
            const float* ap = A + (size_t)(m0 + rA) * K + k0 + hA * 16;
            #pragma unroll
            for (int i = 0; i < 4; i++) axf[i] = *(const float4*)(ap + 4 * i);
            #pragma unroll
            for (int i = 0; i < 4; i++) {
                int kp = kp0 + 4 * i;
                bxk[i][0] = Bp[(size_t)(k0 + 2 * kp) * N + n0 + nB];
                bxk[i][1] = Bp[(size_t)(k0 + 2 * kp + 1) * N + n0 + nB];
            }
        }

        const int r0 = wid * 16 + tg, r1 = r0 + 8;
        #pragma unroll
        for (int ks = 0; ks < 2; ks++) {
            int ca = t4 + 8 * ks;
            uint32_t ah[4] = { sA[r0][ca],     sA[r1][ca],
                               sA[r0][ca + 4], sA[r1][ca + 4] };
            #pragma unroll
            for (int nt = 0; nt < 8; nt++) {
                int n = nt * 8 + tg;
                uint32_t bh_[2] = { sB[n][ca], sB[n][ca + 4] };
                uint32_t bl_[2] = { sB[n][16 + ca], sB[n][16 + ca + 4] };
                mma16816(c[nt], ah, bh_);
                mma16816(c[nt], ah, bl_);
            }
        }
    }

    const int r0 = m0 + wid * 16 + tg, r1 = r0 + 8;
    float sc0 = gg[r0] * rsqrtf(vv[r0] + EPSV), sh0 = bb[r0] - mm[r0] * sc0;
    float sc1 = gg[r1] * rsqrtf(vv[r1] + EPSV), sh1 = bb[r1] - mm[r1] * sc1;
    #pragma unroll
    for (int nt = 0; nt < 8; nt++) {
        int n = n0 + nt * 8 + 2 * t4;
        *(float2*)&Cp[(size_t)r0 * N + n] = make_float2(c[nt][0] * sc0 + sh0,
                                                        c[nt][1] * sc0 + sh0);
        *(float2*)&Cp[(size_t)r1 * N + n] = make_float2(c[nt][2] * sc1 + sh1,
                                                        c[nt][3] * sc1 + sh1);
    }
}

// ---------------------------------------------------------------------------
// Flash attention via warp-level fp16 HMMA (single-term).
// R11 code; __launch_bounds__(256, 2) to fit 2 CTAs/SM -> one wave of 256.
// ---------------------------------------------------------------------------
__global__ __launch_bounds__(256, 2) void attn_mma_kernel(
    const float* __restrict__ qkv, float* __restrict__ y)
{
    __shared__ uint32_t sQ[128][20];
    __shared__ uint32_t sK[64][20];
    __shared__ uint32_t sV[64][36];

    const int tid = threadIdx.x, wid = tid >> 5, lane = tid & 31;
    const int tg = lane >> 2;
    const int t4 = lane & 3;
    const int bh = blockIdx.y, bi = bh >> 2, h = bh & 3;
    const int q0 = blockIdx.x * 128;

    const float* qp = qkv + ((size_t)bi * 512 + h * 128) * NTOK;
    const float* kp = qp + (size_t)32 * NTOK;
    const float* vp = qp + (size_t)64 * NTOK;

    {
        const float scale = 0.17677669529663687f;
        int row = tid & 127, dp0 = tid >> 7;
        #pragma unroll
        for (int dp = dp0; dp < 16; dp += 2) {
            float x0 = qp[(size_t)(2 * dp) * NTOK + q0 + row] * scale;
            float x1 = qp[(size_t)(2 * dp + 1) * NTOK + q0 + row] * scale;
            sQ[row][dp] = pack_h2(x0, x1);
        }
    }
    __syncthreads();

    uint32_t qh[2][4];
    {
        int r0 = wid * 16 + tg, r1 = r0 + 8;
        #pragma unroll
        for (int ks = 0; ks < 2; ks++) {
            int cidx = t4 + 8 * ks;
            qh[ks][0] = sQ[r0][cidx];     qh[ks][1] = sQ[r1][cidx];
            qh[ks][2] = sQ[r0][cidx + 4]; qh[ks][3] = sQ[r1][cidx + 4];
        }
    }

    const int kkey = tid & 63, kdp0 = tid >> 6;
    const int vkp = tid & 31, vd0 = tid >> 5;

    float kx[4][2];
    float2 vx[8];
    {
        #pragma unroll
        for (int i = 0; i < 4; i++) {
            int dp = kdp0 + 4 * i;
            kx[i][0] = kp[(size_t)(2 * dp) * NTOK + kkey];
            kx[i][1] = kp[(size_t)(2 * dp + 1) * NTOK + kkey];
        }
        #pragma unroll
        for (int i = 0; i < 8; i++) {
            int d = vd0 + 8 * i;
            vx[i] = *(const float2*)(vp + (size_t)d * NTOK + 2 * vkp);
        }
    }

    float m0 = -3e38f, m1 = -3e38f, l0 = 0.f, l1 = 0.f;
    float yacc[8][4];
    #pragma unroll
    for (int i = 0; i < 8; i++)
        #pragma unroll
        for (int j = 0; j < 4; j++) yacc[i][j] = 0.f;

    for (int blk = 0; blk < 64; blk++) {
        __syncthreads();
        #pragma unroll
        for (int i = 0; i < 4; i++)
            sK[kkey][kdp0 + 4 * i] = pack_h2(kx[i][0], kx[i][1]);
        #pragma unroll
        for (int i = 0; i < 8; i++)
            sV[vd0 + 8 * i][vkp] = pack_h2(vx[i].x, vx[i].y);
        __syncthreads();

        if (blk < 63) {
            const int k0t = (blk + 1) * 64;
            #pragma unroll
            for (int i = 0; i < 4; i++) {
                int dp = kdp0 + 4 * i;
                kx[i][0] = kp[(size_t)(2 * dp) * NTOK + k0t + kkey];
                kx[i][1] = kp[(size_t)(2 * dp + 1) * NTOK + k0t + kkey];
            }
            #pragma unroll
            for (int i = 0; i < 8; i++) {
                int d = vd0 + 8 * i;
                vx[i] = *(const float2*)(vp + (size_t)d * NTOK + k0t + 2 * vkp);
            }
        }

        float s[8][4];
        #pragma unroll
        for (int nt = 0; nt < 8; nt++) {
            s[nt][0] = s[nt][1] = s[nt][2] = s[nt][3] = 0.f;
            int key = nt * 8 + tg;
            #pragma unroll
            for (int ks = 0; ks < 2; ks++) {
                uint32_t b_[2] = { sK[key][t4 + 8 * ks], sK[key][t4 + 4 + 8 * ks] };
                mma16816(s[nt], qh[ks], b_);
            }
        }

        float mx0 = -3e38f, mx1 = -3e38f;
        #pragma unroll
        for (int nt = 0; nt < 8; nt++) {
            mx0 = fmaxf(mx0, fmaxf(s[nt][0], s[nt][1]));
            mx1 = fmaxf(mx1, fmaxf(s[nt][2], s[nt][3]));
        }
        mx0 = fmaxf(mx0, __shfl_xor_sync(0xffffffffu, mx0, 1));
        mx0 = fmaxf(mx0, __shfl_xor_sync(0xffffffffu, mx0, 2));
        mx1 = fmaxf(mx1, __shfl_xor_sync(0xffffffffu, mx1, 1));
        mx1 = fmaxf(mx1, __shfl_xor_sync(0xffffffffu, mx1, 2));
        float mn0 = fmaxf(m0, mx0), mn1 = fmaxf(m1, mx1);
        float al0 = __expf(m0 - mn0), al1 = __expf(m1 - mn1);
        m0 = mn0; m1 = mn1;

        uint32_t p01[8], p23[8];
        float sum0 = 0.f, sum1 = 0.f;
        #pragma unroll
        for (int nt = 0; nt < 8; nt++) {
            float p0 = __expf(s[nt][0] - mn0);
            float p1 = __expf(s[nt][1] - mn0);
            float p2 = __expf(s[nt][2] - mn1);
            float p3 = __expf(s[nt][3] - mn1);
            sum0 += p0 + p1;  sum1 += p2 + p3;
            p01[nt] = pack_h2(p0, p1);
            p23[nt] = pack_h2(p2, p3);
        }
        sum0 += __shfl_xor_sync(0xffffffffu, sum0, 1);
        sum0 += __shfl_xor_sync(0xffffffffu, sum0, 2);
        sum1 += __shfl_xor_sync(0xffffffffu, sum1, 1);
        sum1 += __shfl_xor_sync(0xffffffffu, sum1, 2);
        l0 = l0 * al0 + sum0;
        l1 = l1 * al1 + sum1;

        #pragma unroll
        for (int dt = 0; dt < 8; dt++) {
            yacc[dt][0] *= al0; yacc[dt][1] *= al0;
            yacc[dt][2] *= al1; yacc[dt][3] *= al1;
        }

        #pragma unroll
        for (int ks = 0; ks < 4; ks++) {
            uint32_t a_[4] = { p01[2 * ks], p23[2 * ks], p01[2 * ks + 1], p23[2 * ks + 1] };
            #pragma unroll
            for (int dt = 0; dt < 8; dt++) {
                int dim = dt * 8 + tg;
                uint32_t b_[2] = { sV[dim][t4 + 8 * ks], sV[dim][t4 + 4 + 8 * ks] };
                mma16816(yacc[dt], a_, b_);
            }
        }
    }

    float li0 = 1.f / l0, li1 = 1.f / l1;
    int tok0 = q0 + wid * 16 + tg;
    #pragma unroll
    for (int dt = 0; dt < 8; dt++) {
        int dim = dt * 8 + t4 * 2;
        float* o = y + ((size_t)(bh * 64 + dim)) * NTOK;
        o[tok0]            = yacc[dt][0] * li0;
        o[NTOK + tok0]     = yacc[dt][1] * li0;
        o[tok0 + 8]        = yacc[dt][2] * li1;
        o[NTOK + tok0 + 8] = yacc[dt][3] * li1;
    }
}

// ---------------------------------------------------------------------------
// Depthwise 3x3 conv + BN accumulated into g_y (restored standalone — R12
// fusion was a measured regression)
// ---------------------------------------------------------------------------
__global__ __launch_bounds__(256) void pe_kernel(
    const float* __restrict__ qkv, float* __restrict__ y,
    const float* __restrict__ w,
    const float* __restrict__ gg, const float* __restrict__ bb,
    const float* __restrict__ mm, const float* __restrict__ vv)
{
    const int idx = blockIdx.x * 256 + threadIdx.x;
    const int bi = idx >> 20;
    const int r  = idx & ((1 << 20) - 1);
    const int c  = r >> 12;
    const int pix = r & 4095;
    const int py = pix >> 6, px = pix & 63;
    const int head = c >> 6, dim = c & 63;

    const float* vch = qkv + ((size_t)bi * 512 + head * 128 + 64 + dim) * NTOK;
    const float* wc = w + c * 9;

    float s = 0.f;
    #pragma unroll
    for (int dy = -1; dy <= 1; dy++) {
        int yy = py + dy;
        if (yy < 0 || yy > 63) continue;
        #pragma unroll
        for (int dx = -1; dx <= 1; dx++) {
            int xx = px + dx;
            if (xx < 0 || xx > 63) continue;
            s += vch[yy * 64 + xx] * wc[(dy + 1) * 3 + (dx + 1)];
        }
    }
    float sc = gg[c] * rsqrtf(vv[c] + EPSV);
    y[idx] += s * sc + (bb[c] - mm[c] * sc);
}

// ---------------------------------------------------------------------------
extern "C" void kernel_launch(void* const* d_in, const int* in_sizes, int n_in,
                              void* d_out, int out_size)
{
    const float* x      = (const float*)d_in[0];
    const float* qkv_w  = (const float*)d_in[1];
    const float* qkv_g  = (const float*)d_in[2];
    const float* qkv_b  = (const float*)d_in[3];
    const float* qkv_m  = (const float*)d_in[4];
    const float* qkv_v  = (const float*)d_in[5];
    const float* proj_w = (const float*)d_in[6];
    const float* proj_g = (const float*)d_in[7];
    const float* proj_b = (const float*)d_in[8];
    const float* proj_m = (const float*)d_in[9];
    const float* proj_v = (const float*)d_in[10];
    const float* pe_w   = (const float*)d_in[11];
    const float* pe_g   = (const float*)d_in[12];
    const float* pe_b   = (const float*)d_in[13];
    const float* pe_m   = (const float*)d_in[14];
    const float* pe_v   = (const float*)d_in[15];
    float* out = (float*)d_out;

    float* qkv_ptr = nullptr;
    float* y_ptr = nullptr;
    cudaGetSymbolAddress((void**)&qkv_ptr, g_qkv);
    cudaGetSymbolAddress((void**)&y_ptr, g_y);

    // 1) QKV 1x1 conv + BN  (512x256 @ 256x4096, per batch)
    gemm_bn_tc<<<dim3(64, 4, 2), 256>>>(qkv_w, x, qkv_ptr, 512, 4096, 256,
                                        qkv_g, qkv_b, qkv_m, qkv_v);
    // 2) HMMA fp16 flash attention -> g_y  (2 CTAs/SM, single wave)
    attn_mma_kernel<<<dim3(32, 8), 256>>>(qkv_ptr, y_ptr);
    // 3) PE depthwise conv + BN accumulate
    pe_kernel<<<8192, 256>>>(qkv_ptr, y_ptr, pe_w, pe_g, pe_b, pe_m, pe_v);
    // 4) proj 1x1 conv + BN -> out
    gemm_bn_tc<<<dim3(64, 2, 2), 256>>>(proj_w, y_ptr, out, 256, 4096, 256,
                                        proj_g, proj_b, proj_m, proj_v);
}